// round 13
// baseline (speedup 1.0000x reference)
#include <cuda_runtime.h>
#include <cstdint>

// GeometricLoss, R13: ONE fused persistent kernel.
// 148 CTAs x 1024 threads (1/SM, all resident -> spin grid-barriers safe).
// Phases: slice stats (deterministic fixed-order combine) -> global count ->
// per-CTA local prefix scan (identical cell table in each CTA's smem) ->
// scatter -> smem point cache -> LANE-PER-QUERY search (register top-6, no
// warp collectives) -> last-CTA fixed-order reduction.
// Selection over unique keys (d2_bits<<32)|pid, <=th gate, exact ring bound
// -> exact jax.lax.top_k (low-index tie-break), deterministic output.

#define NPTS 8192
#define NCH 16
#define KNN 5
#define G 48
#define NCELL (G * G)          // 2304
#define NBLK 148
#define TPB 1024
#define FULLM 0xFFFFFFFFu
typedef unsigned long long ull;
#define SENT 0xFFFFFFFFFFFFFFFFULL
#define FINF __int_as_float(0x7F800000)

__device__ float4 g_pts4[NPTS];     // {x, y, bitcast(pid), 0}
__device__ int    g_count[NCELL];
__device__ int    g_cursor[NCELL];
__device__ float4 g_sliceA[NBLK];   // {sx, sy, sxx, syy}
__device__ float4 g_sliceB[NBLK];   // {mnx, mxx, mny, mxy}
__device__ float  g_partial[NPTS];  // indexed by ORIGINAL pid
__device__ unsigned g_bar;          // spin barrier counter (reset at end)
__device__ unsigned g_ticket;       // final ticket (reset at end)

extern __shared__ char smem_dyn[];  // float4 s_pts[NPTS] + int2 s_cell[NCELL]

// Grid-wide barrier: all NBLK CTAs resident (1/SM), monotone targets.
__device__ __forceinline__ void grid_bar(unsigned target) {
    __syncthreads();
    if (threadIdx.x == 0) {
        __threadfence();
        atomicAdd(&g_bar, 1u);
        while (*(volatile unsigned*)&g_bar < target) __nanosleep(64);
        __threadfence();
    }
    __syncthreads();
}

// Per-thread sorted top-6 insert; precondition d2 <= th. Updates th.
__device__ __forceinline__ void ins6t(ull* b, float d2, unsigned pid,
                                      float& th) {
    ull key = ((ull)__float_as_uint(d2) << 32) | pid;
    if (key < b[5]) {
        b[5] = key;
#pragma unroll
        for (int t = 5; t > 0; t--) {
            if (b[t] < b[t - 1]) { ull tmp = b[t]; b[t] = b[t - 1]; b[t - 1] = tmp; }
        }
        unsigned hi = (unsigned)(b[5] >> 32);
        th = (hi == 0xFFFFFFFFu) ? FINF : __uint_as_float(hi);
    }
}

__global__ __launch_bounds__(TPB, 1)
void fused_kernel(const float* __restrict__ outputs,
                  const float2* __restrict__ points,
                  float* __restrict__ out) {
    float4* s_pts  = (float4*)smem_dyn;
    int2*   s_cell = (int2*)(smem_dyn + NPTS * sizeof(float4));
    __shared__ float s_red[256];
    __shared__ float s_gp[8];        // minx, miny, invw, invh, cw
    __shared__ int   s_wsum[32];
    __shared__ float s_rsum[TPB];
    __shared__ bool  is_last;

    const int tid = threadIdx.x;
    const int lane = tid & 31, warp = tid >> 5;
    const int b = blockIdx.x;
    const int lo = (b * NPTS) / NBLK;
    const int hi = ((b + 1) * NPTS) / NBLK;
    const int cnt = hi - lo;                   // 55 or 56

    // ---------- P0: zero counts (CTA0) + slice stats ----------
    if (b == 0)
        for (int i = tid; i < NCELL; i += TPB) g_count[i] = 0;

    float2 myp = make_float2(0.0f, 0.0f);
    if (tid < cnt) myp = points[lo + tid];
    {
        bool act = tid < cnt;
        float sx = act ? myp.x : 0.0f, sy = act ? myp.y : 0.0f;
        float sxx = act ? myp.x * myp.x : 0.0f;
        float syy = act ? myp.y * myp.y : 0.0f;
        float mnx = act ? myp.x : 1e30f, mxx = act ? myp.x : -1e30f;
        float mny = act ? myp.y : 1e30f, mxy = act ? myp.y : -1e30f;
#pragma unroll
        for (int off = 16; off > 0; off >>= 1) {
            sx  += __shfl_xor_sync(FULLM, sx,  off);
            sy  += __shfl_xor_sync(FULLM, sy,  off);
            sxx += __shfl_xor_sync(FULLM, sxx, off);
            syy += __shfl_xor_sync(FULLM, syy, off);
            mnx = fminf(mnx, __shfl_xor_sync(FULLM, mnx, off));
            mxx = fmaxf(mxx, __shfl_xor_sync(FULLM, mxx, off));
            mny = fminf(mny, __shfl_xor_sync(FULLM, mny, off));
            mxy = fmaxf(mxy, __shfl_xor_sync(FULLM, mxy, off));
        }
        if (lane == 0) {
            s_red[warp] = sx;        s_red[32 + warp] = sy;
            s_red[64 + warp] = sxx;  s_red[96 + warp] = syy;
            s_red[128 + warp] = mnx; s_red[160 + warp] = mxx;
            s_red[192 + warp] = mny; s_red[224 + warp] = mxy;
        }
        __syncthreads();
        if (tid == 0) {
            float a = 0, c = 0, d = 0, e = 0;
            float f = 1e30f, g = -1e30f, h = 1e30f, k = -1e30f;
            for (int w = 0; w < 32; w++) {          // fixed order
                a += s_red[w]; c += s_red[32 + w];
                d += s_red[64 + w]; e += s_red[96 + w];
                f = fminf(f, s_red[128 + w]); g = fmaxf(g, s_red[160 + w]);
                h = fminf(h, s_red[192 + w]); k = fmaxf(k, s_red[224 + w]);
            }
            g_sliceA[b] = make_float4(a, c, d, e);
            g_sliceB[b] = make_float4(f, g, h, k);
        }
    }
    grid_bar(NBLK);

    // ---------- P1: combine slices (warp 0, fixed structure) ----------
    if (warp == 0) {
        float sx = 0, sy = 0, sxx = 0, syy = 0;
        float mnx = 1e30f, mxx = -1e30f, mny = 1e30f, mxy = -1e30f;
        for (int i = lane; i < NBLK; i += 32) {   // fixed per-lane order
            float4 A = g_sliceA[i], B = g_sliceB[i];
            sx += A.x; sy += A.y; sxx += A.z; syy += A.w;
            mnx = fminf(mnx, B.x); mxx = fmaxf(mxx, B.y);
            mny = fminf(mny, B.z); mxy = fmaxf(mxy, B.w);
        }
#pragma unroll
        for (int off = 16; off > 0; off >>= 1) {  // fixed butterfly
            sx  += __shfl_xor_sync(FULLM, sx,  off);
            sy  += __shfl_xor_sync(FULLM, sy,  off);
            sxx += __shfl_xor_sync(FULLM, sxx, off);
            syy += __shfl_xor_sync(FULLM, syy, off);
            mnx = fminf(mnx, __shfl_xor_sync(FULLM, mnx, off));
            mxx = fmaxf(mxx, __shfl_xor_sync(FULLM, mxx, off));
            mny = fminf(mny, __shfl_xor_sync(FULLM, mny, off));
            mxy = fmaxf(mxy, __shfl_xor_sync(FULLM, mxy, off));
        }
        if (lane == 0) {
            const float invn = 1.0f / (float)NPTS;
            float mx = sx * invn, my = sy * invn;
            float vx = fmaxf(sxx * invn - mx * mx, 0.0f);
            float vy = fmaxf(syy * invn - my * my, 0.0f);
            float sdx = sqrtf(vx), sdy = sqrtf(vy);
            float lox = fmaxf(mnx, mx - 2.5f * sdx);
            float hix = fminf(mxx, mx + 2.5f * sdx);
            float loy = fmaxf(mny, my - 2.5f * sdy);
            float hiy = fminf(mxy, my + 2.5f * sdy);
            if (!(hix > lox)) { lox = mnx; hix = mxx; }
            if (!(hiy > loy)) { loy = mny; hiy = mxy; }
            float w = hix - lox, h = hiy - loy;
            s_gp[0] = lox; s_gp[1] = loy;
            s_gp[2] = (w > 0.0f) ? (float)G / w : 0.0f;
            s_gp[3] = (h > 0.0f) ? (float)G / h : 0.0f;
            s_gp[4] = fminf(w / (float)G, h / (float)G);
        }
    }
    __syncthreads();
    const float minx = s_gp[0], miny = s_gp[1];
    const float invw = s_gp[2], invh = s_gp[3];
    const float cw = s_gp[4];

    // ---------- P2: count ----------
    int mycell = 0;
    if (tid < cnt) {
        int cx = min(max((int)((myp.x - minx) * invw), 0), G - 1);
        int cy = min(max((int)((myp.y - miny) * invh), 0), G - 1);
        mycell = cy * G + cx;
        atomicAdd(&g_count[mycell], 1);
    }
    grid_bar(2 * NBLK);

    // ---------- P3: per-CTA local scan -> s_cell; CTA0 writes cursors ----
    {
        const int base = tid * 3;
        int c0 = (base     < NCELL) ? g_count[base]     : 0;
        int c1 = (base + 1 < NCELL) ? g_count[base + 1] : 0;
        int c2 = (base + 2 < NCELL) ? g_count[base + 2] : 0;
        int run = c0 + c1 + c2;
        int inc = run;
#pragma unroll
        for (int off = 1; off < 32; off <<= 1) {
            int y = __shfl_up_sync(FULLM, inc, off);
            if (lane >= off) inc += y;
        }
        if (lane == 31) s_wsum[warp] = inc;
        __syncthreads();
        if (warp == 0) {
            int x = s_wsum[lane];
#pragma unroll
            for (int off = 1; off < 32; off <<= 1) {
                int y = __shfl_up_sync(FULLM, x, off);
                if (lane >= off) x += y;
            }
            s_wsum[lane] = x;
        }
        __syncthreads();
        int pre = ((warp > 0) ? s_wsum[warp - 1] : 0) + inc - run;
        if (base < NCELL) {
            s_cell[base] = make_int2(pre, c0);
            if (b == 0) g_cursor[base] = pre;
        }
        if (base + 1 < NCELL) {
            s_cell[base + 1] = make_int2(pre + c0, c1);
            if (b == 0) g_cursor[base + 1] = pre + c0;
        }
        if (base + 2 < NCELL) {
            s_cell[base + 2] = make_int2(pre + c0 + c1, c2);
            if (b == 0) g_cursor[base + 2] = pre + c0 + c1;
        }
    }
    grid_bar(3 * NBLK);

    // ---------- P4: scatter (order-independent downstream) ----------
    if (tid < cnt) {
        int slot = atomicAdd(&g_cursor[mycell], 1);
        g_pts4[slot] = make_float4(myp.x, myp.y,
                                   __int_as_float(lo + tid), 0.0f);
    }
    grid_bar(4 * NBLK);

    // ---------- P5: cache all binned points in smem ----------
#pragma unroll
    for (int i = tid; i < NPTS; i += TPB) s_pts[i] = g_pts4[i];
    __syncthreads();

    // ---------- P6: lane-per-query search over slots [lo, hi) ----------
    if (tid < cnt) {
        const int s = lo + tid;                 // my binned slot
        const float4 Q = s_pts[s];
        const float qx = Q.x, qy = Q.y;
        const unsigned qpid = (unsigned)__float_as_int(Q.z);
        const int cx = min(max((int)((qx - minx) * invw), 0), G - 1);
        const int cy = min(max((int)((qy - miny) * invh), 0), G - 1);

        ull bk[6];
#pragma unroll
        for (int t = 0; t < 6; t++) bk[t] = SENT;
        float th = FINF;

        // disk D=1: 3 contiguous row ranges
        {
            int xa = max(cx - 1, 0), xb = min(cx + 1, G - 1);
            int ya = max(cy - 1, 0), yb = min(cy + 1, G - 1);
            for (int y = ya; y <= yb; y++) {
                int2 c0 = s_cell[y * G + xa];
                int2 c1 = s_cell[y * G + xb];
                int e = c1.x + c1.y;
                for (int j = c0.x; j < e; j++) {
                    float4 P = s_pts[j];
                    float dx = qx - P.x, dy = qy - P.y;
                    float d2 = fmaf(dx, dx, dy * dy);
                    if (d2 <= th)
                        ins6t(bk, d2, (unsigned)__float_as_int(P.z), th);
                }
            }
        }

        // expanding rings with exact termination bound
        int D = 1;
        while (D < G) {
            float bnd = (float)D * cw;
            if (th <= bnd * bnd) break;
            const int d = D + 1;
            int xa = max(cx - d, 0), xb = min(cx + d, G - 1);
            if (cy - d >= 0) {
                int y = cy - d;
                int2 c0 = s_cell[y * G + xa];
                int2 c1 = s_cell[y * G + xb];
                int e = c1.x + c1.y;
                for (int j = c0.x; j < e; j++) {
                    float4 P = s_pts[j];
                    float dx = qx - P.x, dy = qy - P.y;
                    float d2 = fmaf(dx, dx, dy * dy);
                    if (d2 <= th)
                        ins6t(bk, d2, (unsigned)__float_as_int(P.z), th);
                }
            }
            if (cy + d <= G - 1) {
                int y = cy + d;
                int2 c0 = s_cell[y * G + xa];
                int2 c1 = s_cell[y * G + xb];
                int e = c1.x + c1.y;
                for (int j = c0.x; j < e; j++) {
                    float4 P = s_pts[j];
                    float dx = qx - P.x, dy = qy - P.y;
                    float d2 = fmaf(dx, dx, dy * dy);
                    if (d2 <= th)
                        ins6t(bk, d2, (unsigned)__float_as_int(P.z), th);
                }
            }
            int ya = max(cy - d + 1, 0), yb = min(cy + d - 1, G - 1);
            for (int y = ya; y <= yb; y++) {
                if (cx - d >= 0) {
                    int2 c = s_cell[y * G + cx - d];
                    int e = c.x + c.y;
                    for (int j = c.x; j < e; j++) {
                        float4 P = s_pts[j];
                        float dx = qx - P.x, dy = qy - P.y;
                        float d2 = fmaf(dx, dx, dy * dy);
                        if (d2 <= th)
                            ins6t(bk, d2, (unsigned)__float_as_int(P.z), th);
                    }
                }
                if (cx + d <= G - 1) {
                    int2 c = s_cell[y * G + cx + d];
                    int e = c.x + c.y;
                    for (int j = c.x; j < e; j++) {
                        float4 P = s_pts[j];
                        float dx = qx - P.x, dy = qy - P.y;
                        float d2 = fmaf(dx, dx, dy * dy);
                        if (d2 <= th)
                            ins6t(bk, d2, (unsigned)__float_as_int(P.z), th);
                    }
                }
            }
            D = d;
        }

        // epilogue: bk[0] = self (min key); bk[1..5] = neighbors
        const float4* oq = (const float4*)(outputs + (size_t)qpid * NCH);
        float4 a0 = oq[0], a1 = oq[1], a2 = oq[2], a3 = oq[3];
        float ssum = 0.0f;
#pragma unroll
        for (int r = 1; r <= KNN; r++) {
            unsigned nb = (unsigned)(bk[r] & 0xFFFFFFFFULL);
            const float4* on = (const float4*)(outputs + (size_t)nb * NCH);
            float4 n0 = on[0], n1 = on[1], n2 = on[2], n3 = on[3];
            float acc = 0.0f, dd;
            dd = a0.x - n0.x; acc = fmaf(dd, dd, acc);
            dd = a0.y - n0.y; acc = fmaf(dd, dd, acc);
            dd = a0.z - n0.z; acc = fmaf(dd, dd, acc);
            dd = a0.w - n0.w; acc = fmaf(dd, dd, acc);
            dd = a1.x - n1.x; acc = fmaf(dd, dd, acc);
            dd = a1.y - n1.y; acc = fmaf(dd, dd, acc);
            dd = a1.z - n1.z; acc = fmaf(dd, dd, acc);
            dd = a1.w - n1.w; acc = fmaf(dd, dd, acc);
            dd = a2.x - n2.x; acc = fmaf(dd, dd, acc);
            dd = a2.y - n2.y; acc = fmaf(dd, dd, acc);
            dd = a2.z - n2.z; acc = fmaf(dd, dd, acc);
            dd = a2.w - n2.w; acc = fmaf(dd, dd, acc);
            dd = a3.x - n3.x; acc = fmaf(dd, dd, acc);
            dd = a3.y - n3.y; acc = fmaf(dd, dd, acc);
            dd = a3.z - n3.z; acc = fmaf(dd, dd, acc);
            dd = a3.w - n3.w; acc = fmaf(dd, dd, acc);
            ssum += sqrtf(acc);
        }
        g_partial[qpid] = ssum;
    }

    // ---------- final ticket: last CTA reduces (fixed order) ----------
    __syncthreads();
    if (tid == 0) {
        __threadfence();
        is_last = (atomicAdd(&g_ticket, 1u) == NBLK - 1);
    }
    __syncthreads();
    if (is_last) {
        __threadfence();
        float acc = 0.0f;
        for (int j = tid; j < NPTS; j += TPB) acc += g_partial[j];
        s_rsum[tid] = acc;
        __syncthreads();
        for (int st = TPB / 2; st > 0; st >>= 1) {
            if (tid < st) s_rsum[tid] += s_rsum[tid + st];
            __syncthreads();
        }
        if (tid == 0) {
            out[0] = s_rsum[0] / (float)(NPTS * KNN);
            g_ticket = 0;   // safe: all CTAs passed every spin before here
            g_bar = 0;
        }
    }
}

extern "C" void kernel_launch(void* const* d_in, const int* in_sizes, int n_in,
                              void* d_out, int out_size) {
    const float*  outputs = (const float*)d_in[0];
    const float2* points  = (const float2*)d_in[1];
    float* out = (float*)d_out;

    const int smem_bytes = NPTS * sizeof(float4) + NCELL * sizeof(int2);
    cudaFuncSetAttribute(fused_kernel,
                         cudaFuncAttributeMaxDynamicSharedMemorySize,
                         smem_bytes);
    fused_kernel<<<NBLK, TPB, smem_bytes>>>(outputs, points, out);
}

// round 14
// speedup vs baseline: 1.1994x; 1.1994x over previous
#include <cuda_runtime.h>
#include <cstdint>

// GeometricLoss, R14: fused persistent kernel + HYBRID search.
// 148 CTAs x 1024 (1/SM, all resident -> spin grid-barriers safe).
// Build phases as R13 (slice stats -> count -> per-CTA scan -> scatter ->
// smem cache). Search: P6a lane-per-query capped at D<=3 (dense bulk, no
// collectives); unterminated queries go to a CTA-local overflow list; P6b
// re-solves them warp-per-query (lane-per-cell rings + exact warp merge).
// Both paths: unique keys (d2_bits<<32)|pid, <=th gate, exact ring bound ->
// identical exact top-6, jax.lax.top_k tie-break, deterministic output.

#define NPTS 8192
#define NCH 16
#define KNN 5
#define G 48
#define NCELL (G * G)          // 2304
#define NBLK 148
#define TPB 1024
#define DCAP 3                 // lane-phase ring cap
#define FULLM 0xFFFFFFFFu
typedef unsigned long long ull;
#define SENT 0xFFFFFFFFFFFFFFFFULL
#define FINF __int_as_float(0x7F800000)

__device__ float4 g_pts4[NPTS];     // {x, y, bitcast(pid), 0}
__device__ int    g_count[NCELL];
__device__ int    g_cursor[NCELL];
__device__ float4 g_sliceA[NBLK];   // {sx, sy, sxx, syy}
__device__ float4 g_sliceB[NBLK];   // {mnx, mxx, mny, mxy}
__device__ float  g_partial[NPTS];  // indexed by ORIGINAL pid
__device__ unsigned g_bar;          // spin barrier counter (reset at end)
__device__ unsigned g_ticket;       // final ticket (reset at end)

extern __shared__ char smem_dyn[];  // float4 s_pts[NPTS] + int2 s_cell[NCELL]

__device__ __forceinline__ void grid_bar(unsigned target) {
    __syncthreads();
    if (threadIdx.x == 0) {
        __threadfence();
        atomicAdd(&g_bar, 1u);
        while (*(volatile unsigned*)&g_bar < target) __nanosleep(64);
        __threadfence();
    }
    __syncthreads();
}

// Per-thread sorted top-6 insert; updates th (6th-best d2 or +inf).
__device__ __forceinline__ void ins6t(ull* b, float d2, unsigned pid,
                                      float& th) {
    ull key = ((ull)__float_as_uint(d2) << 32) | pid;
    if (key < b[5]) {
        b[5] = key;
#pragma unroll
        for (int t = 5; t > 0; t--) {
            if (b[t] < b[t - 1]) { ull tmp = b[t]; b[t] = b[t - 1]; b[t - 1] = tmp; }
        }
        unsigned hi = (unsigned)(b[5] >> 32);
        th = (hi == 0xFFFFFFFFu) ? FINF : __uint_as_float(hi);
    }
}

// Exact warp merge over unique keys (lane r ends holding rank-r key in rk).
__device__ __forceinline__ void merge6(ull* b, ull& rk, float& th, int lane) {
    if (lane < 6 && rk != SENT && rk < b[5]) {
        b[5] = rk;
#pragma unroll
        for (int t = 5; t > 0; t--) {
            if (b[t] < b[t - 1]) { ull tmp = b[t]; b[t] = b[t - 1]; b[t - 1] = tmp; }
        }
    }
    ull newrk = SENT;
#pragma unroll
    for (int r = 0; r < 6; r++) {
        ull m = b[0];
#pragma unroll
        for (int off = 16; off > 0; off >>= 1) {
            ull o = __shfl_xor_sync(FULLM, m, off);
            if (o < m) m = o;
        }
        if (lane == r) newrk = m;
        if (b[0] == m && m != SENT) {
            b[0] = b[1]; b[1] = b[2]; b[2] = b[3];
            b[3] = b[4]; b[4] = b[5]; b[5] = SENT;
        }
    }
    rk = newrk;
    ull k5 = __shfl_sync(FULLM, newrk, 5);
    unsigned hi5 = (unsigned)(k5 >> 32);
    th = (hi5 == 0xFFFFFFFFu) ? FINF : __uint_as_float(hi5);
}

__global__ __launch_bounds__(TPB, 1)
void fused_kernel(const float* __restrict__ outputs,
                  const float2* __restrict__ points,
                  float* __restrict__ out) {
    float4* s_pts  = (float4*)smem_dyn;
    int2*   s_cell = (int2*)(smem_dyn + NPTS * sizeof(float4));
    __shared__ float s_red[256];
    __shared__ float s_gp[8];
    __shared__ int   s_wsum[32];
    __shared__ float s_rsum[TPB];
    __shared__ int   s_ovf[64];
    __shared__ int   s_novf;
    __shared__ bool  is_last;

    const int tid = threadIdx.x;
    const int lane = tid & 31, warp = tid >> 5;
    const int b = blockIdx.x;
    const int lo = (b * NPTS) / NBLK;
    const int hic = ((b + 1) * NPTS) / NBLK;
    const int cnt = hic - lo;                  // 55 or 56

    // ---------- P0: zero counts (CTA0) + slice stats ----------
    if (b == 0)
        for (int i = tid; i < NCELL; i += TPB) g_count[i] = 0;
    if (tid == 0) s_novf = 0;

    float2 myp = make_float2(0.0f, 0.0f);
    if (tid < cnt) myp = points[lo + tid];
    {
        bool act = tid < cnt;
        float sx = act ? myp.x : 0.0f, sy = act ? myp.y : 0.0f;
        float sxx = act ? myp.x * myp.x : 0.0f;
        float syy = act ? myp.y * myp.y : 0.0f;
        float mnx = act ? myp.x : 1e30f, mxx = act ? myp.x : -1e30f;
        float mny = act ? myp.y : 1e30f, mxy = act ? myp.y : -1e30f;
#pragma unroll
        for (int off = 16; off > 0; off >>= 1) {
            sx  += __shfl_xor_sync(FULLM, sx,  off);
            sy  += __shfl_xor_sync(FULLM, sy,  off);
            sxx += __shfl_xor_sync(FULLM, sxx, off);
            syy += __shfl_xor_sync(FULLM, syy, off);
            mnx = fminf(mnx, __shfl_xor_sync(FULLM, mnx, off));
            mxx = fmaxf(mxx, __shfl_xor_sync(FULLM, mxx, off));
            mny = fminf(mny, __shfl_xor_sync(FULLM, mny, off));
            mxy = fmaxf(mxy, __shfl_xor_sync(FULLM, mxy, off));
        }
        if (lane == 0) {
            s_red[warp] = sx;        s_red[32 + warp] = sy;
            s_red[64 + warp] = sxx;  s_red[96 + warp] = syy;
            s_red[128 + warp] = mnx; s_red[160 + warp] = mxx;
            s_red[192 + warp] = mny; s_red[224 + warp] = mxy;
        }
        __syncthreads();
        if (tid == 0) {
            float a = 0, c = 0, d = 0, e = 0;
            float f = 1e30f, g = -1e30f, h = 1e30f, k = -1e30f;
            for (int w = 0; w < 32; w++) {          // fixed order
                a += s_red[w]; c += s_red[32 + w];
                d += s_red[64 + w]; e += s_red[96 + w];
                f = fminf(f, s_red[128 + w]); g = fmaxf(g, s_red[160 + w]);
                h = fminf(h, s_red[192 + w]); k = fmaxf(k, s_red[224 + w]);
            }
            g_sliceA[b] = make_float4(a, c, d, e);
            g_sliceB[b] = make_float4(f, g, h, k);
        }
    }
    grid_bar(NBLK);

    // ---------- P1: combine slices (warp 0, fixed structure) ----------
    if (warp == 0) {
        float sx = 0, sy = 0, sxx = 0, syy = 0;
        float mnx = 1e30f, mxx = -1e30f, mny = 1e30f, mxy = -1e30f;
        for (int i = lane; i < NBLK; i += 32) {
            float4 A = g_sliceA[i], B = g_sliceB[i];
            sx += A.x; sy += A.y; sxx += A.z; syy += A.w;
            mnx = fminf(mnx, B.x); mxx = fmaxf(mxx, B.y);
            mny = fminf(mny, B.z); mxy = fmaxf(mxy, B.w);
        }
#pragma unroll
        for (int off = 16; off > 0; off >>= 1) {
            sx  += __shfl_xor_sync(FULLM, sx,  off);
            sy  += __shfl_xor_sync(FULLM, sy,  off);
            sxx += __shfl_xor_sync(FULLM, sxx, off);
            syy += __shfl_xor_sync(FULLM, syy, off);
            mnx = fminf(mnx, __shfl_xor_sync(FULLM, mnx, off));
            mxx = fmaxf(mxx, __shfl_xor_sync(FULLM, mxx, off));
            mny = fminf(mny, __shfl_xor_sync(FULLM, mny, off));
            mxy = fmaxf(mxy, __shfl_xor_sync(FULLM, mxy, off));
        }
        if (lane == 0) {
            const float invn = 1.0f / (float)NPTS;
            float mx = sx * invn, my = sy * invn;
            float vx = fmaxf(sxx * invn - mx * mx, 0.0f);
            float vy = fmaxf(syy * invn - my * my, 0.0f);
            float sdx = sqrtf(vx), sdy = sqrtf(vy);
            float lox = fmaxf(mnx, mx - 2.5f * sdx);
            float hix = fminf(mxx, mx + 2.5f * sdx);
            float loy = fmaxf(mny, my - 2.5f * sdy);
            float hiy = fminf(mxy, my + 2.5f * sdy);
            if (!(hix > lox)) { lox = mnx; hix = mxx; }
            if (!(hiy > loy)) { loy = mny; hiy = mxy; }
            float w = hix - lox, h = hiy - loy;
            s_gp[0] = lox; s_gp[1] = loy;
            s_gp[2] = (w > 0.0f) ? (float)G / w : 0.0f;
            s_gp[3] = (h > 0.0f) ? (float)G / h : 0.0f;
            s_gp[4] = fminf(w / (float)G, h / (float)G);
        }
    }
    __syncthreads();
    const float minx = s_gp[0], miny = s_gp[1];
    const float invw = s_gp[2], invh = s_gp[3];
    const float cw = s_gp[4];

    // ---------- P2: count ----------
    int mycell = 0;
    if (tid < cnt) {
        int cx = min(max((int)((myp.x - minx) * invw), 0), G - 1);
        int cy = min(max((int)((myp.y - miny) * invh), 0), G - 1);
        mycell = cy * G + cx;
        atomicAdd(&g_count[mycell], 1);
    }
    grid_bar(2 * NBLK);

    // ---------- P3: per-CTA local scan -> s_cell; CTA0 writes cursors ----
    {
        const int base = tid * 3;
        int c0 = (base     < NCELL) ? g_count[base]     : 0;
        int c1 = (base + 1 < NCELL) ? g_count[base + 1] : 0;
        int c2 = (base + 2 < NCELL) ? g_count[base + 2] : 0;
        int run = c0 + c1 + c2;
        int inc = run;
#pragma unroll
        for (int off = 1; off < 32; off <<= 1) {
            int y = __shfl_up_sync(FULLM, inc, off);
            if (lane >= off) inc += y;
        }
        if (lane == 31) s_wsum[warp] = inc;
        __syncthreads();
        if (warp == 0) {
            int x = s_wsum[lane];
#pragma unroll
            for (int off = 1; off < 32; off <<= 1) {
                int y = __shfl_up_sync(FULLM, x, off);
                if (lane >= off) x += y;
            }
            s_wsum[lane] = x;
        }
        __syncthreads();
        int pre = ((warp > 0) ? s_wsum[warp - 1] : 0) + inc - run;
        if (base < NCELL) {
            s_cell[base] = make_int2(pre, c0);
            if (b == 0) g_cursor[base] = pre;
        }
        if (base + 1 < NCELL) {
            s_cell[base + 1] = make_int2(pre + c0, c1);
            if (b == 0) g_cursor[base + 1] = pre + c0;
        }
        if (base + 2 < NCELL) {
            s_cell[base + 2] = make_int2(pre + c0 + c1, c2);
            if (b == 0) g_cursor[base + 2] = pre + c0 + c1;
        }
    }
    grid_bar(3 * NBLK);

    // ---------- P4: scatter (order-independent downstream) ----------
    if (tid < cnt) {
        int slot = atomicAdd(&g_cursor[mycell], 1);
        g_pts4[slot] = make_float4(myp.x, myp.y,
                                   __int_as_float(lo + tid), 0.0f);
    }
    grid_bar(4 * NBLK);

    // ---------- P5: cache all binned points in smem ----------
#pragma unroll
    for (int i = tid; i < NPTS; i += TPB) s_pts[i] = g_pts4[i];
    __syncthreads();

    // ---------- P6a: lane-per-query, ring cap DCAP; overflow list ----------
    if (tid < cnt) {
        const int s = lo + tid;
        const float4 Q = s_pts[s];
        const float qx = Q.x, qy = Q.y;
        const unsigned qpid = (unsigned)__float_as_int(Q.z);
        const int cx = min(max((int)((qx - minx) * invw), 0), G - 1);
        const int cy = min(max((int)((qy - miny) * invh), 0), G - 1);

        ull bk[6];
#pragma unroll
        for (int t = 0; t < 6; t++) bk[t] = SENT;
        float th = FINF;

        // disk D=1: 3 contiguous row ranges
        {
            int xa = max(cx - 1, 0), xb = min(cx + 1, G - 1);
            int ya = max(cy - 1, 0), yb = min(cy + 1, G - 1);
            for (int y = ya; y <= yb; y++) {
                int2 c0 = s_cell[y * G + xa];
                int2 c1 = s_cell[y * G + xb];
                int e = c1.x + c1.y;
                for (int j = c0.x; j < e; j++) {
                    float4 P = s_pts[j];
                    float dx = qx - P.x, dy = qy - P.y;
                    float d2 = fmaf(dx, dx, dy * dy);
                    if (d2 <= th)
                        ins6t(bk, d2, (unsigned)__float_as_int(P.z), th);
                }
            }
        }
        int D = 1;
        bool done = (th <= (float)D * cw * (float)D * cw);
        while (!done && D < DCAP) {
            const int d = D + 1;
            int xa = max(cx - d, 0), xb = min(cx + d, G - 1);
#pragma unroll 1
            for (int side = 0; side < 2; side++) {
                int y = side ? cy + d : cy - d;
                if ((unsigned)y < G) {
                    int2 c0 = s_cell[y * G + xa];
                    int2 c1 = s_cell[y * G + xb];
                    int e = c1.x + c1.y;
                    for (int j = c0.x; j < e; j++) {
                        float4 P = s_pts[j];
                        float dx = qx - P.x, dy = qy - P.y;
                        float d2 = fmaf(dx, dx, dy * dy);
                        if (d2 <= th)
                            ins6t(bk, d2, (unsigned)__float_as_int(P.z), th);
                    }
                }
            }
            int ya = max(cy - d + 1, 0), yb = min(cy + d - 1, G - 1);
            for (int y = ya; y <= yb; y++) {
#pragma unroll 1
                for (int side = 0; side < 2; side++) {
                    int x = side ? cx + d : cx - d;
                    if ((unsigned)x < G) {
                        int2 c = s_cell[y * G + x];
                        int e = c.x + c.y;
                        for (int j = c.x; j < e; j++) {
                            float4 P = s_pts[j];
                            float dx = qx - P.x, dy = qy - P.y;
                            float d2 = fmaf(dx, dx, dy * dy);
                            if (d2 <= th)
                                ins6t(bk, d2, (unsigned)__float_as_int(P.z), th);
                        }
                    }
                }
            }
            D = d;
            done = (th <= (float)D * cw * (float)D * cw);
        }

        if (!done) {
            int o = atomicAdd(&s_novf, 1);
            s_ovf[o] = s;                        // re-solve in P6b
        } else {
            // epilogue: bk[0]=self, bk[1..5]=neighbors
            const float4* oq = (const float4*)(outputs + (size_t)qpid * NCH);
            float4 a0 = oq[0], a1 = oq[1], a2 = oq[2], a3 = oq[3];
            float ssum = 0.0f;
#pragma unroll
            for (int r = 1; r <= KNN; r++) {
                unsigned nb = (unsigned)(bk[r] & 0xFFFFFFFFULL);
                const float4* on = (const float4*)(outputs + (size_t)nb * NCH);
                float4 n0 = on[0], n1 = on[1], n2 = on[2], n3 = on[3];
                float acc = 0.0f, dd;
                dd = a0.x - n0.x; acc = fmaf(dd, dd, acc);
                dd = a0.y - n0.y; acc = fmaf(dd, dd, acc);
                dd = a0.z - n0.z; acc = fmaf(dd, dd, acc);
                dd = a0.w - n0.w; acc = fmaf(dd, dd, acc);
                dd = a1.x - n1.x; acc = fmaf(dd, dd, acc);
                dd = a1.y - n1.y; acc = fmaf(dd, dd, acc);
                dd = a1.z - n1.z; acc = fmaf(dd, dd, acc);
                dd = a1.w - n1.w; acc = fmaf(dd, dd, acc);
                dd = a2.x - n2.x; acc = fmaf(dd, dd, acc);
                dd = a2.y - n2.y; acc = fmaf(dd, dd, acc);
                dd = a2.z - n2.z; acc = fmaf(dd, dd, acc);
                dd = a2.w - n2.w; acc = fmaf(dd, dd, acc);
                dd = a3.x - n3.x; acc = fmaf(dd, dd, acc);
                dd = a3.y - n3.y; acc = fmaf(dd, dd, acc);
                dd = a3.z - n3.z; acc = fmaf(dd, dd, acc);
                dd = a3.w - n3.w; acc = fmaf(dd, dd, acc);
                ssum += sqrtf(acc);
            }
            g_partial[qpid] = ssum;
        }
    }
    __syncthreads();

    // ---------- P6b: warp-per-query on overflow (rare sparse tail) --------
    {
        const int novf = s_novf;
        for (int o = warp; o < novf; o += TPB / 32) {
            const int s = s_ovf[o];
            const float4 Q = s_pts[s];
            const float qx = Q.x, qy = Q.y;
            const unsigned qpid = (unsigned)__float_as_int(Q.z);
            const int cx = min(max((int)((qx - minx) * invw), 0), G - 1);
            const int cy = min(max((int)((qy - miny) * invh), 0), G - 1);

            ull bk[6];
#pragma unroll
            for (int t = 0; t < 6; t++) bk[t] = SENT;
            ull rk = SENT;
            float th = FINF;

            // disk D=1 flattened across lanes
            {
                int xa = max(cx - 1, 0), xb = min(cx + 1, G - 1);
                int ya = max(cy - 1, 0), yb = min(cy + 1, G - 1);
                int s0 = 0, l0 = 0, s1 = 0, l1 = 0, s2 = 0, l2 = 0;
                {
                    int2 c0 = s_cell[ya * G + xa];
                    int2 c1 = s_cell[ya * G + xb];
                    s0 = c0.x; l0 = c1.x + c1.y - c0.x;
                }
                if (ya + 1 <= yb) {
                    int2 c0 = s_cell[(ya + 1) * G + xa];
                    int2 c1 = s_cell[(ya + 1) * G + xb];
                    s1 = c0.x; l1 = c1.x + c1.y - c0.x;
                }
                if (ya + 2 <= yb) {
                    int2 c0 = s_cell[(ya + 2) * G + xa];
                    int2 c1 = s_cell[(ya + 2) * G + xb];
                    s2 = c0.x; l2 = c1.x + c1.y - c0.x;
                }
                int o1 = l0, o2 = l0 + l1, tot = o2 + l2;
                for (int t = lane; t < tot; t += 32) {
                    int j;
                    if (t < o1)      j = s0 + t;
                    else if (t < o2) j = s1 + (t - o1);
                    else             j = s2 + (t - o2);
                    float4 P = s_pts[j];
                    float dx = qx - P.x, dy = qy - P.y;
                    float d2 = fmaf(dx, dx, dy * dy);
                    if (d2 <= th)
                        ins6t(bk, d2, (unsigned)__float_as_int(P.z), th);
                }
            }
            merge6(bk, rk, th, lane);

            int D = 1;
            while (D < G) {
                float bnd = (float)D * cw;
                if (th <= bnd * bnd) break;
                const int d = D + 1;
                const int ncells = 8 * d;
                bool dirty = false;
                for (int tb = 0; tb < ncells; tb += 32) {
                    int t = tb + lane;
                    if (t < ncells) {
                        int x, y;
                        int rowspan = 2 * d + 1;
                        if (t < 2 * rowspan) {
                            int row = t / rowspan, k = t % rowspan;
                            x = cx - d + k;
                            y = row ? cy + d : cy - d;
                        } else {
                            int t2 = t - 2 * rowspan;
                            int colspan = 2 * d - 1;
                            int col = t2 / colspan, k = t2 % colspan;
                            x = col ? cx + d : cx - d;
                            y = cy - d + 1 + k;
                        }
                        if ((unsigned)x < G && (unsigned)y < G) {
                            int2 ci = s_cell[y * G + x];
                            int e = ci.x + ci.y;
                            for (int j = ci.x; j < e; j++) {
                                float4 P = s_pts[j];
                                float dx = qx - P.x, dy = qy - P.y;
                                float d2 = fmaf(dx, dx, dy * dy);
                                if (d2 <= th) {
                                    ins6t(bk, d2,
                                          (unsigned)__float_as_int(P.z), th);
                                    dirty = true;
                                }
                            }
                        }
                    }
                }
                if (__ballot_sync(FULLM, dirty)) merge6(bk, rk, th, lane);
                D = d;
            }

            // epilogue: lanes 1..5 hold neighbor ranks
            float sv = 0.0f;
            if (lane >= 1 && lane <= KNN) {
                int nb = (int)(rk & 0xFFFFFFFFULL);
                const float4* oq = (const float4*)(outputs + (size_t)qpid * NCH);
                const float4* on = (const float4*)(outputs + (size_t)nb * NCH);
                float acc = 0.0f;
#pragma unroll
                for (int c = 0; c < NCH / 4; c++) {
                    float4 a = oq[c];
                    float4 bb = on[c];
                    float d;
                    d = a.x - bb.x; acc = fmaf(d, d, acc);
                    d = a.y - bb.y; acc = fmaf(d, d, acc);
                    d = a.z - bb.z; acc = fmaf(d, d, acc);
                    d = a.w - bb.w; acc = fmaf(d, d, acc);
                }
                sv = sqrtf(acc);
            }
#pragma unroll
            for (int off = 16; off > 0; off >>= 1)
                sv += __shfl_xor_sync(FULLM, sv, off);
            if (lane == 0) g_partial[qpid] = sv;
        }
    }

    // ---------- final ticket: last CTA reduces (fixed order) ----------
    __syncthreads();
    if (tid == 0) {
        __threadfence();
        is_last = (atomicAdd(&g_ticket, 1u) == NBLK - 1);
    }
    __syncthreads();
    if (is_last) {
        __threadfence();
        float acc = 0.0f;
        for (int j = tid; j < NPTS; j += TPB) acc += g_partial[j];
        s_rsum[tid] = acc;
        __syncthreads();
        for (int st = TPB / 2; st > 0; st >>= 1) {
            if (tid < st) s_rsum[tid] += s_rsum[tid + st];
            __syncthreads();
        }
        if (tid == 0) {
            out[0] = s_rsum[0] / (float)(NPTS * KNN);
            g_ticket = 0;   // safe: all CTAs passed every spin before here
            g_bar = 0;
        }
    }
}

extern "C" void kernel_launch(void* const* d_in, const int* in_sizes, int n_in,
                              void* d_out, int out_size) {
    const float*  outputs = (const float*)d_in[0];
    const float2* points  = (const float2*)d_in[1];
    float* out = (float*)d_out;

    const int smem_bytes = NPTS * sizeof(float4) + NCELL * sizeof(int2);
    cudaFuncSetAttribute(fused_kernel,
                         cudaFuncAttributeMaxDynamicSharedMemorySize,
                         smem_bytes);
    fused_kernel<<<NBLK, TPB, smem_bytes>>>(outputs, points, out);
}